// round 14
// baseline (speedup 1.0000x reference)
#include <cuda_runtime.h>
#include <cuda_bf16.h>

// Recall_53077205844588: masked mean of remapped `predicted` over gt!=0.
// predicted: [B=32, F=512, T=2048] fp32; gt: same shape int32 in {0,1}.
// result = sum_{gt!=0} predicted[b, f==0?1:f, t==0?1:t] / count, or 0 if count==0.
//
// Perfectly-balanced single-wave grid: 1184 blocks = 148 SMs x 8 CTAs, so every
// SM gets exactly 8 CTAs (full 64 warps/SM) and there is no partial wave 2.
// Work distributed in whole rows (1 row = 512 float4 = 2 iters of 256 thr):
// first 992 blocks take 14 rows, remaining 192 take 13 (992*14+192*13=16384).
// Trip count is one of two compile-time values -> fully unrolled bodies with
// LDG immediate offsets (max 108KB), zero per-iteration address ALU.
// t==0 column remap stays hoisted (tid==0, even iters). The f==0 row remap no
// longer aligns to blocks: main loop streams all rows plainly; the <=32 blocks
// containing an image-first row run a small fix-up replacing that row's masked
// contributions with the next row's (+0.3% traffic).

#define NTHREADS 256
#define NBLOCKS 1184                          // 148 SMs * 8 CTAs
#define ROW_VEC 512                           // float4 per row (T=2048 floats)
#define ROWS_TOTAL 16384                      // B*F
#define BIG_BLOCKS 992                        // 992*14 + 192*13 = 16384 rows

__device__ float        g_partial_sum[NBLOCKS];
__device__ unsigned int g_partial_cnt[NBLOCKS];
__device__ unsigned int g_done_counter = 0;   // atomicInc wraps to 0 -> graph-replay safe

template<int NROWS>
__device__ __forceinline__ void stream_rows(const float4* __restrict__ pp,
                                            const int4*   __restrict__ gp,
                                            bool t0b, float& s, unsigned int& c)
{
    #pragma unroll
    for (int i = 0; i < NROWS * 2; i++) {
        float4 p = __ldcs(pp + i * NTHREADS);   // offset i*4KB: immediate
        int4   g = __ldcs(gp + i * NTHREADS);
        if (((i & 1) == 0) && t0b) p.x = p.y;   // col remap t==0 -> t'=1
        if (g.x) { s += p.x; c++; }
        if (g.y) { s += p.y; c++; }
        if (g.z) { s += p.z; c++; }
        if (g.w) { s += p.w; c++; }
    }
}

__device__ __forceinline__ void block_reduce_write(float v, unsigned int c,
                                                   float* out_s, unsigned int* out_c)
{
    #pragma unroll
    for (int off = 16; off > 0; off >>= 1) {
        v += __shfl_down_sync(0xffffffffu, v, off);
        c += __shfl_down_sync(0xffffffffu, c, off);
    }
    __shared__ float        s_sum[NTHREADS / 32];
    __shared__ unsigned int s_cnt[NTHREADS / 32];
    const int lane = threadIdx.x & 31;
    const int wid  = threadIdx.x >> 5;
    if (lane == 0) { s_sum[wid] = v; s_cnt[wid] = c; }
    __syncthreads();
    if (wid == 0) {
        float        bs = (lane < NTHREADS / 32) ? s_sum[lane] : 0.0f;
        unsigned int bc = (lane < NTHREADS / 32) ? s_cnt[lane] : 0u;
        #pragma unroll
        for (int off = 4; off > 0; off >>= 1) {
            bs += __shfl_down_sync(0xffffffffu, bs, off);
            bc += __shfl_down_sync(0xffffffffu, bc, off);
        }
        if (lane == 0) { *out_s = bs; *out_c = bc; }
    }
    __syncthreads();
}

__global__ __launch_bounds__(NTHREADS, 8) void recall_fused_kernel(
    const float* __restrict__ pred,
    const int*   __restrict__ gt,
    float*       __restrict__ out)
{
    const int tid = threadIdx.x;
    const int bid = blockIdx.x;

    const int  nrows = (bid < BIG_BLOCKS) ? 14 : 13;
    const int  start = bid * 13 + min(bid, BIG_BLOCKS);     // first row of block
    const bool t0b   = (tid == 0);

    const float4* pp = (const float4*)pred + start * ROW_VEC + tid;
    const int4*   gp = (const int4*)gt   + start * ROW_VEC + tid;

    float        local_sum = 0.0f;
    unsigned int local_cnt = 0;

    if (nrows == 14) stream_rows<14>(pp, gp, t0b, local_sum, local_cnt);
    else             stream_rows<13>(pp, gp, t0b, local_sum, local_cnt);

    // f==0 fix-up: image-first rows are global rows r0 with r0 % 512 == 0.
    // A block holds at most one. Replace that row's masked contributions
    // (computed from row r0 in the main loop) with row r0+1's, both t-remapped.
    {
        const int r0 = ((start + nrows - 1) >> 9) << 9;     // last f0-row <= block end
        if (r0 >= start) {
            const float4* pa = (const float4*)pred + r0 * ROW_VEC + tid;
            const int4*   ga = (const int4*)gt   + r0 * ROW_VEC + tid;
            #pragma unroll
            for (int j = 0; j < 2; j++) {
                float4 p0 = __ldg(pa + j * NTHREADS);           // row r0 (subtract)
                float4 p1 = __ldg(pa + ROW_VEC + j * NTHREADS); // row r0+1 (add)
                int4   g  = __ldg(ga + j * NTHREADS);
                if (j == 0 && t0b) { p0.x = p0.y; p1.x = p1.y; }
                if (g.x) local_sum += p1.x - p0.x;
                if (g.y) local_sum += p1.y - p0.y;
                if (g.z) local_sum += p1.z - p0.z;
                if (g.w) local_sum += p1.w - p0.w;
            }
        }
    }

    float        blk_sum;
    unsigned int blk_cnt;
    block_reduce_write(local_sum, local_cnt, &blk_sum, &blk_cnt);

    __shared__ bool s_is_last;
    if (threadIdx.x == 0) {
        g_partial_sum[bid] = blk_sum;
        g_partial_cnt[bid] = blk_cnt;
        __threadfence();
        unsigned int prev = atomicInc(&g_done_counter, NBLOCKS - 1);
        s_is_last = (prev == NBLOCKS - 1);
    }
    __syncthreads();

    if (s_is_last) {
        float        fs = 0.0f;
        unsigned int fc = 0;
        #pragma unroll
        for (int j = 0; j < (NBLOCKS + NTHREADS - 1) / NTHREADS; j++) {
            const int idx = j * NTHREADS + threadIdx.x;
            if (idx < NBLOCKS) {
                fs += g_partial_sum[idx];
                fc += g_partial_cnt[idx];
            }
        }
        float        tot_sum;
        unsigned int tot_cnt;
        block_reduce_write(fs, fc, &tot_sum, &tot_cnt);
        if (threadIdx.x == 0) {
            out[0] = (tot_cnt > 0u) ? (tot_sum / (float)tot_cnt) : 0.0f;
        }
    }
}

extern "C" void kernel_launch(void* const* d_in, const int* in_sizes, int n_in,
                              void* d_out, int out_size)
{
    const float* pred = (const float*)d_in[0];
    const int*   gt   = (const int*)d_in[1];
    float*       out  = (float*)d_out;

    recall_fused_kernel<<<NBLOCKS, NTHREADS>>>(pred, gt, out);
}